// round 7
// baseline (speedup 1.0000x reference)
#include <cuda_runtime.h>
#include <stdint.h>

// out[b,q,k] (FLOAT32 0.0/1.0) =
//   (q-k >= -off) & (0 <= q-k < win) & (expl[q,k] != 0) & (qseg[b,q] == kseg[b,k])
//
// Ground truth: explicit/segments are int32 device buffers; the 4 scalars are
// 4-byte int32 device buffers; output buffer is 4 bytes/element and compared as
// float32 (bool reference upcast) — so we must store 1.0f, not integer 1.

__global__ void __launch_bounds__(256)
mask4_kernel(const int* __restrict__ expl,   // [qlen, klen] i32 0/1
             const int* __restrict__ qseg,   // [B, qlen]
             const int* __restrict__ kseg,   // [B, klen]
             float*     __restrict__ out,    // [B, qlen, klen] f32
             int qlen, int klen, int B,
             int off, int win,
             const int* off_dev, const int* win_dev,
             int ngroups)
{
    int g = blockIdx.x * blockDim.x + threadIdx.x;
    if (g >= ngroups) return;

    if (off_dev) off = __ldg(off_dev);
    if (win_dev) win = __ldg(win_dev);

    // batch-innermost: all B batches of a (q,k)-chunk run together so the
    // explicit row is fetched from DRAM once and reused via L2.
    const int b = g % B;
    const int c = g / B;
    const int cpr = klen >> 2;
    const int q   = c / cpr;
    const int k0  = (c - q * cpr) << 2;

    float4* outv = reinterpret_cast<float4*>(
        out + ((long long)(b * qlen + q)) * klen + k0);

    const int kmax = q + (off < 0 ? off : 0);
    const int kmin = q - win + 1;

    if (k0 > kmax || (k0 + 3) < kmin) {
        *outv = make_float4(0.f, 0.f, 0.f, 0.f);
        return;
    }

    const int4 e  = __ldg((const int4*)(expl + (long long)q * klen + k0));
    const int  qs = __ldg(qseg + b * qlen + q);
    const int4 ks = __ldg((const int4*)(kseg + (long long)b * klen + k0));

    const int d = q - k0;
    float4 r;
    r.x = ((d   >= -off) & (d   >= 0) & (d   < win) & (e.x != 0) & (qs == ks.x)) ? 1.f : 0.f;
    r.y = ((d-1 >= -off) & (d-1 >= 0) & (d-1 < win) & (e.y != 0) & (qs == ks.y)) ? 1.f : 0.f;
    r.z = ((d-2 >= -off) & (d-2 >= 0) & (d-2 < win) & (e.z != 0) & (qs == ks.z)) ? 1.f : 0.f;
    r.w = ((d-3 >= -off) & (d-3 >= 0) & (d-3 < win) & (e.w != 0) & (qs == ks.w)) ? 1.f : 0.f;
    *outv = r;
}

// Elementwise fallback (klen % 4 != 0; not expected for 8192).
__global__ void __launch_bounds__(256)
mask1_kernel(const int* __restrict__ expl,
             const int* __restrict__ qseg,
             const int* __restrict__ kseg,
             float*     __restrict__ out,
             int qlen, int klen, int off, int win,
             const int* off_dev, const int* win_dev,
             long long total)
{
    long long idx = (long long)blockIdx.x * blockDim.x + threadIdx.x;
    if (idx >= total) return;
    if (off_dev) off = __ldg(off_dev);
    if (win_dev) win = __ldg(win_dev);
    const int k = (int)(idx % klen);
    const long long row = idx / klen;
    const int q = (int)(row % qlen);
    const int b = (int)(row / qlen);
    const int d = q - k;
    const bool ok = (d >= -off) & (d >= 0) & (d < win)
                  & (expl[(long long)q * klen + k] != 0)
                  & (qseg[row] == kseg[(long long)b * klen + k]);
    out[idx] = ok ? 1.f : 0.f;
}

// Decode a size-1 scalar input. mode: 0 = immediate value, 1 = device pointer.
static int read_scalar(const void* p, int* mode, const int** dev_ptr)
{
    *mode = 0; *dev_ptr = nullptr;
    const uint64_t v = (uint64_t)(uintptr_t)p;
    if (v < 0x100000000ull)         return (int)(int64_t)v;   // value-in-pointer
    if (v >= 0xFFFFFFFF00000000ull) return (int)(int64_t)v;

    cudaPointerAttributes a;
    cudaError_t e = cudaPointerGetAttributes(&a, p);
    if (e == cudaSuccess) {
        if (a.type == cudaMemoryTypeHost || a.type == cudaMemoryTypeUnregistered)
            return *(const int*)p;
        if (a.type == cudaMemoryTypeManaged && a.hostPointer)
            return *(const int*)a.hostPointer;
        if (a.type == cudaMemoryTypeDevice) { *mode = 1; *dev_ptr = (const int*)p; return 0; }
    }
    cudaGetLastError();
    return *(const int*)p;
}

extern "C" void kernel_launch(void* const* d_in, const int* in_sizes, int n_in,
                              void* d_out, int out_size)
{
    // 0=explicit_mask, 1=q_segment_ids, 2=kv_segment_ids,
    // 3=q_len, 4=k_len, 5=causal_offset, 6=window
    const int* expl = (const int*)d_in[0];
    const int* qseg = (const int*)d_in[1];
    const int* kseg = (const int*)d_in[2];
    float*     out  = (float*)d_out;

    const long long s_expl = in_sizes[0];                // qlen*klen
    const int B    = (int)((long long)out_size / s_expl);
    const int qlen = in_sizes[1] / B;
    const int klen = in_sizes[2] / B;

    int m5, m6;
    const int *p5, *p6;
    int off = read_scalar(d_in[5], &m5, &p5);
    int win = read_scalar(d_in[6], &m6, &p6);

    const int* off_dev = (m5 == 1) ? p5 : nullptr;
    const int* win_dev = (m6 == 1) ? p6 : nullptr;

    if ((klen & 3) == 0) {
        const int ngroups = (int)(((long long)out_size) >> 2);
        const int threads = 256;
        const int blocks  = (ngroups + threads - 1) / threads;
        mask4_kernel<<<blocks, threads>>>(expl, qseg, kseg, out,
                                          qlen, klen, B, off, win,
                                          off_dev, win_dev, ngroups);
    } else {
        const long long total = out_size;
        const int threads = 256;
        const long long blocks = (total + threads - 1) / threads;
        mask1_kernel<<<(unsigned)blocks, threads>>>(expl, qseg, kseg, out,
                                                    qlen, klen, off, win,
                                                    off_dev, win_dev, total);
    }
}

// round 8
// speedup vs baseline: 1.3319x; 1.3319x over previous
#include <cuda_runtime.h>
#include <stdint.h>

// out[b,q,k] (f32 0/1) = (kmin <= k <= kmax) & (expl[q,k]!=0) & (qseg[b,q]==kseg[b,k])
//   kmax = q + min(off,0), kmin = q - win + 1   (collapses causal+offset+window)
//
// One block per output row (b,q); batch-inner row order so the 4 batches of the
// same q run adjacently -> explicit row read from DRAM once, reused via L2.

__global__ void __launch_bounds__(256)
mask_row_kernel(const int* __restrict__ expl,   // [qlen, klen]
                const int* __restrict__ qseg,   // [B, qlen]
                const int* __restrict__ kseg,   // [B, klen]
                float*     __restrict__ out,    // [B, qlen, klen]
                int qlen, int klen, int B,
                int off_imm, int win_imm,
                const int* off_dev, const int* win_dev)
{
    const int rowid = blockIdx.x;          // = q * B + b  (batch-inner)
    const int b = rowid % B;
    const int q = rowid / B;

    const int off = off_dev ? __ldg(off_dev) : off_imm;
    const int win = win_dev ? __ldg(win_dev) : win_imm;

    const int kmax = q + (off < 0 ? off : 0);
    const int kmin = q - win + 1;
    const int qs   = __ldg(qseg + b * qlen + q);

    float4*     orow = reinterpret_cast<float4*>(out + ((long long)b * qlen + q) * klen);
    const int4* erow = reinterpret_cast<const int4*>(expl + (long long)q * klen);
    const int4* krow = reinterpret_cast<const int4*>(kseg + (long long)b * klen);

    const int n4 = klen >> 2;
    const float4 zero = make_float4(0.f, 0.f, 0.f, 0.f);

    #pragma unroll 2
    for (int i = threadIdx.x; i < n4; i += blockDim.x) {
        const int k0 = i << 2;
        if (k0 > kmax || (k0 + 3) < kmin) {
            orow[i] = zero;
        } else {
            const int4 e  = __ldg(erow + i);
            const int4 ks = __ldg(krow + i);
            float4 r;
            r.x = ((k0   >= kmin) & (k0   <= kmax) & (e.x != 0) & (qs == ks.x)) ? 1.f : 0.f;
            r.y = ((k0+1 >= kmin) & (k0+1 <= kmax) & (e.y != 0) & (qs == ks.y)) ? 1.f : 0.f;
            r.z = ((k0+2 >= kmin) & (k0+2 <= kmax) & (e.z != 0) & (qs == ks.z)) ? 1.f : 0.f;
            r.w = ((k0+3 >= kmin) & (k0+3 <= kmax) & (e.w != 0) & (qs == ks.w)) ? 1.f : 0.f;
            orow[i] = r;
        }
    }
}

// Elementwise fallback (klen % 4 != 0; not expected for 8192).
__global__ void __launch_bounds__(256)
mask1_kernel(const int* __restrict__ expl,
             const int* __restrict__ qseg,
             const int* __restrict__ kseg,
             float*     __restrict__ out,
             int qlen, int klen, int off, int win,
             const int* off_dev, const int* win_dev,
             long long total)
{
    long long idx = (long long)blockIdx.x * blockDim.x + threadIdx.x;
    if (idx >= total) return;
    if (off_dev) off = __ldg(off_dev);
    if (win_dev) win = __ldg(win_dev);
    const int k = (int)(idx % klen);
    const long long row = idx / klen;
    const int q = (int)(row % qlen);
    const int b = (int)(row / qlen);
    const int d = q - k;
    const bool ok = (d >= -off) & (d >= 0) & (d < win)
                  & (expl[(long long)q * klen + k] != 0)
                  & (qseg[row] == kseg[(long long)b * klen + k]);
    out[idx] = ok ? 1.f : 0.f;
}

// Decode a size-1 scalar input. mode: 0 = immediate value, 1 = device pointer.
static int read_scalar(const void* p, int* mode, const int** dev_ptr)
{
    *mode = 0; *dev_ptr = nullptr;
    const uint64_t v = (uint64_t)(uintptr_t)p;
    if (v < 0x100000000ull)         return (int)(int64_t)v;
    if (v >= 0xFFFFFFFF00000000ull) return (int)(int64_t)v;

    cudaPointerAttributes a;
    cudaError_t e = cudaPointerGetAttributes(&a, p);
    if (e == cudaSuccess) {
        if (a.type == cudaMemoryTypeHost || a.type == cudaMemoryTypeUnregistered)
            return *(const int*)p;
        if (a.type == cudaMemoryTypeManaged && a.hostPointer)
            return *(const int*)a.hostPointer;
        if (a.type == cudaMemoryTypeDevice) { *mode = 1; *dev_ptr = (const int*)p; return 0; }
    }
    cudaGetLastError();
    return *(const int*)p;
}

extern "C" void kernel_launch(void* const* d_in, const int* in_sizes, int n_in,
                              void* d_out, int out_size)
{
    // 0=explicit_mask, 1=q_segment_ids, 2=kv_segment_ids,
    // 3=q_len, 4=k_len, 5=causal_offset, 6=window
    const int* expl = (const int*)d_in[0];
    const int* qseg = (const int*)d_in[1];
    const int* kseg = (const int*)d_in[2];
    float*     out  = (float*)d_out;

    const long long s_expl = in_sizes[0];                // qlen*klen
    const int B    = (int)((long long)out_size / s_expl);
    const int qlen = in_sizes[1] / B;
    const int klen = in_sizes[2] / B;

    int m5, m6;
    const int *p5, *p6;
    const int off = read_scalar(d_in[5], &m5, &p5);
    const int win = read_scalar(d_in[6], &m6, &p6);
    const int* off_dev = (m5 == 1) ? p5 : nullptr;
    const int* win_dev = (m6 == 1) ? p6 : nullptr;

    if ((klen & 3) == 0) {
        const int nrows = B * qlen;
        mask_row_kernel<<<nrows, 256>>>(expl, qseg, kseg, out,
                                        qlen, klen, B, off, win,
                                        off_dev, win_dev);
    } else {
        const long long total = out_size;
        const int threads = 256;
        const long long blocks = (total + threads - 1) / threads;
        mask1_kernel<<<(unsigned)blocks, threads>>>(expl, qseg, kseg, out,
                                                    qlen, klen, off, win,
                                                    off_dev, win_dev, total);
    }
}